// round 1
// baseline (speedup 1.0000x reference)
#include <cuda_runtime.h>
#include <math.h>

#define Bsz 4
#define Nn 1024
#define Dd 1024
#define Hh 8
#define HD 128
#define ROWS (Bsz * Nn)          // 4096
#define MAXNBR 192

// ---------------- scratch (static device globals; no allocation) ------------
__device__ float g_normed[ROWS * Dd];     // 16 MB  LN1 output
__device__ float g_h[ROWS * Dd];          // 16 MB  x + attn (residual stream)
__device__ float g_normed2[ROWS * Dd];    // 16 MB  LN2 output
__device__ float g_mlp1[ROWS * 4 * Dd];   // 64 MB  gelu(normed2 @ W1 + b1)
__device__ int   g_nbr_idx[ROWS * MAXNBR];
__device__ int   g_nbr_cnt[ROWS];

// ---------------- LayerNorm: one block per row ------------------------------
__global__ void ln_kernel(const float* __restrict__ in,
                          const float* __restrict__ gamma,
                          const float* __restrict__ beta,
                          float* __restrict__ out) {
    int row = blockIdx.x;
    int tid = threadIdx.x;
    const float* p = in + (size_t)row * Dd;
    float s = 0.f, s2 = 0.f;
    for (int i = tid; i < Dd; i += 256) {
        float v = p[i];
        s += v; s2 += v * v;
    }
    __shared__ float rs[256], rs2[256];
    rs[tid] = s; rs2[tid] = s2;
    __syncthreads();
    for (int o = 128; o; o >>= 1) {
        if (tid < o) { rs[tid] += rs[tid + o]; rs2[tid] += rs2[tid + o]; }
        __syncthreads();
    }
    float mu = rs[0] * (1.f / Dd);
    float var = rs2[0] * (1.f / Dd) - mu * mu;
    float inv = rsqrtf(var + 1e-5f);
    float* q = out + (size_t)row * Dd;
    for (int i = tid; i < Dd; i += 256)
        q[i] = (p[i] - mu) * inv * gamma[i] + beta[i];
}

// ---------------- neighbor-list build: one block per (b,q) row --------------
__global__ void build_nbr_kernel(const int* __restrict__ adj) {
    int row = blockIdx.x;                 // b*N + q
    __shared__ int cnt;
    if (threadIdx.x == 0) cnt = 0;
    __syncthreads();
    const int* arow = adj + (size_t)row * Nn;
    for (int k = threadIdx.x; k < Nn; k += 256) {
        if (arow[k] > 0) {
            int pos = atomicAdd(&cnt, 1);
            if (pos < MAXNBR) g_nbr_idx[row * MAXNBR + pos] = k;
        }
    }
    __syncthreads();
    if (threadIdx.x == 0) g_nbr_cnt[row] = min(cnt, MAXNBR);
}

// ---------------- sparse attention + residual: one block per (b,q) ----------
// 8 warps = 8 heads. Writes g_h = x + attn_out.
__global__ void attn_kernel(const float* __restrict__ x,
                            const float* __restrict__ stoich,
                            const float* __restrict__ gW,
                            const float* __restrict__ gb) {
    int row = blockIdx.x;
    int b = row >> 10;
    int tid = threadIdx.x;

    __shared__ float qrow[Dd];
    __shared__ float gate[MAXNBR];
    __shared__ int   nbr_s[MAXNBR];
    __shared__ float sc[Hh][MAXNBR];

    int cnt = g_nbr_cnt[row];

    // load q row (LN1 output) into smem: 256 float4
    ((float4*)qrow)[tid] = ((const float4*)(g_normed + (size_t)row * Dd))[tid];

    float st = stoich[row];
    for (int j = tid; j < cnt; j += 256) {
        int k = g_nbr_idx[row * MAXNBR + j];
        nbr_s[j] = k;
        gate[j] = 1.f / (1.f + expf(-(st * gW[k] + gb[k])));
    }
    __syncthreads();

    int wid = tid >> 5, lane = tid & 31;
    const float* base = g_normed + (size_t)b * Nn * Dd;
    float4 qv = ((const float4*)qrow)[wid * 32 + lane];

    const float scale = 0.08838834764831845f;  // 1/sqrt(128)
    float m = -INFINITY;
    for (int j = 0; j < cnt; j++) {
        int k = nbr_s[j];
        float4 kv = ((const float4*)(base + (size_t)k * Dd + wid * HD))[lane];
        float d = qv.x * kv.x + qv.y * kv.y + qv.z * kv.z + qv.w * kv.w;
#pragma unroll
        for (int o = 16; o; o >>= 1) d += __shfl_xor_sync(0xffffffffu, d, o);
        float s = d * scale * gate[j];
        if (lane == 0) sc[wid][j] = s;
        m = fmaxf(m, s);
    }
    __syncwarp();

    float Z = 0.f;
    for (int j = lane; j < cnt; j += 32) Z += expf(sc[wid][j] - m);
#pragma unroll
    for (int o = 16; o; o >>= 1) Z += __shfl_xor_sync(0xffffffffu, Z, o);
    float invZ = 1.f / Z;

    float4 acc = make_float4(0.f, 0.f, 0.f, 0.f);
    for (int j = 0; j < cnt; j++) {
        float p = expf(sc[wid][j] - m) * invZ;
        int k = nbr_s[j];
        float4 kv = ((const float4*)(base + (size_t)k * Dd + wid * HD))[lane];
        acc.x += p * kv.x; acc.y += p * kv.y; acc.z += p * kv.z; acc.w += p * kv.w;
    }

    size_t off = (size_t)row * Dd + wid * HD + lane * 4;
    float4 xv = *(const float4*)(x + off);
    float4 o4 = make_float4(xv.x + acc.x, xv.y + acc.y, xv.z + acc.z, xv.w + acc.w);
    *(float4*)(g_h + off) = o4;
}

// ---------------- SGEMM 128x128x16, 256 threads, 8x8 per thread -------------
__device__ __forceinline__ float gelu_exact(float v) {
    return 0.5f * v * (1.f + erff(v * 0.70710678118654752f));
}

template <int ACT>  // 1: gelu epilogue; 0: +residual epilogue
__global__ void sgemm_kernel(const float* __restrict__ A,
                             const float* __restrict__ B,
                             const float* __restrict__ bias,
                             const float* __restrict__ res,
                             float* __restrict__ C,
                             int M, int N, int K) {
    const int BK = 16, TM = 8, TN = 8;
    __shared__ float As[BK][128];
    __shared__ float Bs[BK][128];

    int tid = threadIdx.x;
    int br = blockIdx.y, bc = blockIdx.x;

    int aRow  = tid >> 2;   // 0..63
    int aCol4 = tid & 3;    // float4 slot in 16-wide K tile
    int bRow  = tid >> 5;   // 0..7
    int bCol4 = tid & 31;   // float4 slot in 128-wide N tile

    int tr = tid >> 4, tc = tid & 15;
    float acc[TM][TN] = {};

    for (int k0 = 0; k0 < K; k0 += BK) {
#pragma unroll
        for (int t = 0; t < 2; t++) {
            int r = aRow + t * 64;
            float4 v = *(const float4*)&A[(size_t)(br * 128 + r) * K + k0 + aCol4 * 4];
            As[aCol4 * 4 + 0][r] = v.x;
            As[aCol4 * 4 + 1][r] = v.y;
            As[aCol4 * 4 + 2][r] = v.z;
            As[aCol4 * 4 + 3][r] = v.w;
        }
#pragma unroll
        for (int t = 0; t < 2; t++) {
            int r = bRow + t * 8;
            float4 v = *(const float4*)&B[(size_t)(k0 + r) * N + bc * 128 + bCol4 * 4];
            *(float4*)&Bs[r][bCol4 * 4] = v;
        }
        __syncthreads();

#pragma unroll
        for (int kk = 0; kk < BK; kk++) {
            float ra[TM], rb[TN];
#pragma unroll
            for (int i = 0; i < TM; i++) ra[i] = As[kk][tr * TM + i];
#pragma unroll
            for (int j = 0; j < TN; j++) rb[j] = Bs[kk][tc * TN + j];
#pragma unroll
            for (int i = 0; i < TM; i++)
#pragma unroll
                for (int j = 0; j < TN; j++) acc[i][j] += ra[i] * rb[j];
        }
        __syncthreads();
    }

#pragma unroll
    for (int i = 0; i < TM; i++) {
        int row = br * 128 + tr * TM + i;
#pragma unroll
        for (int j = 0; j < TN; j++) {
            int col = bc * 128 + tc * TN + j;
            float v = acc[i][j] + bias[col];
            if (ACT) {
                v = gelu_exact(v);
            } else {
                v += res[(size_t)row * N + col];
            }
            C[(size_t)row * N + col] = v;
        }
    }
}

// ---------------- launch -----------------------------------------------------
extern "C" void kernel_launch(void* const* d_in, const int* in_sizes, int n_in,
                              void* d_out, int out_size) {
    const float* x      = (const float*)d_in[0];
    const int*   adj    = (const int*)d_in[1];
    const float* stoich = (const float*)d_in[2];
    const float* ln1_g  = (const float*)d_in[3];
    const float* ln1_b  = (const float*)d_in[4];
    const float* ln2_g  = (const float*)d_in[5];
    const float* ln2_b  = (const float*)d_in[6];
    const float* W1     = (const float*)d_in[7];
    const float* b1     = (const float*)d_in[8];
    const float* W2     = (const float*)d_in[9];
    const float* b2     = (const float*)d_in[10];
    const float* gW     = (const float*)d_in[11];
    const float* gb     = (const float*)d_in[12];
    float* out = (float*)d_out;

    float *normed, *hbuf, *normed2, *mlp1;
    cudaGetSymbolAddress((void**)&normed,  g_normed);
    cudaGetSymbolAddress((void**)&hbuf,    g_h);
    cudaGetSymbolAddress((void**)&normed2, g_normed2);
    cudaGetSymbolAddress((void**)&mlp1,    g_mlp1);

    // 1. LN1
    ln_kernel<<<ROWS, 256>>>(x, ln1_g, ln1_b, normed);
    // 2. neighbor lists
    build_nbr_kernel<<<ROWS, 256>>>(adj);
    // 3. sparse attention + residual -> g_h
    attn_kernel<<<ROWS, 256>>>(x, stoich, gW, gb);
    // 4. LN2
    ln_kernel<<<ROWS, 256>>>(hbuf, ln2_g, ln2_b, normed2);
    // 5. mlp1 = gelu(normed2 @ W1 + b1)   [4096 x 4096]
    {
        dim3 grid(4 * Dd / 128, ROWS / 128);
        sgemm_kernel<1><<<grid, 256>>>(normed2, W1, b1, nullptr, mlp1,
                                       ROWS, 4 * Dd, Dd);
    }
    // 6. out = mlp1 @ W2 + b2 + g_h      [4096 x 1024]
    {
        dim3 grid(Dd / 128, ROWS / 128);
        sgemm_kernel<0><<<grid, 256>>>(mlp1, W2, b2, hbuf, out,
                                       ROWS, Dd, 4 * Dd);
    }
}

// round 3
// speedup vs baseline: 1.0006x; 1.0006x over previous
#include <cuda_runtime.h>
#include <math.h>

#define Bsz 4
#define Nn 1024
#define Dd 1024
#define Hh 8
#define HD 128
#define ROWS (Bsz * Nn)          // 4096
#define MAXNBR 192

// ---------------- scratch (static device globals; no allocation) ------------
__device__ float g_normed[ROWS * Dd];     // 16 MB  LN1 output
__device__ float g_h[ROWS * Dd];          // 16 MB  x + attn (residual stream)
__device__ float g_normed2[ROWS * Dd];    // 16 MB  LN2 output
__device__ float g_mlp1[ROWS * 4 * Dd];   // 64 MB  gelu(normed2 @ W1 + b1)
__device__ int   g_nbr_idx[ROWS * MAXNBR];
__device__ int   g_nbr_cnt[ROWS];

// ---------------- LayerNorm: one block per row ------------------------------
__global__ void ln_kernel(const float* __restrict__ in,
                          const float* __restrict__ gamma,
                          const float* __restrict__ beta,
                          float* __restrict__ out) {
    int row = blockIdx.x;
    int tid = threadIdx.x;
    const float* p = in + (size_t)row * Dd;
    float s = 0.f, s2 = 0.f;
    for (int i = tid; i < Dd; i += 256) {
        float v = p[i];
        s += v; s2 += v * v;
    }
    __shared__ float rs[256], rs2[256];
    rs[tid] = s; rs2[tid] = s2;
    __syncthreads();
    for (int o = 128; o; o >>= 1) {
        if (tid < o) { rs[tid] += rs[tid + o]; rs2[tid] += rs2[tid + o]; }
        __syncthreads();
    }
    float mu = rs[0] * (1.f / Dd);
    float var = rs2[0] * (1.f / Dd) - mu * mu;
    float inv = rsqrtf(var + 1e-5f);
    float* q = out + (size_t)row * Dd;
    for (int i = tid; i < Dd; i += 256)
        q[i] = (p[i] - mu) * inv * gamma[i] + beta[i];
}

// ---------------- neighbor-list build: one block per (b,q) row --------------
__global__ void build_nbr_kernel(const int* __restrict__ adj) {
    int row = blockIdx.x;                 // b*N + q
    __shared__ int cnt;
    if (threadIdx.x == 0) cnt = 0;
    __syncthreads();
    const int* arow = adj + (size_t)row * Nn;
    for (int k = threadIdx.x; k < Nn; k += 256) {
        if (arow[k] > 0) {
            int pos = atomicAdd(&cnt, 1);
            if (pos < MAXNBR) g_nbr_idx[row * MAXNBR + pos] = k;
        }
    }
    __syncthreads();
    if (threadIdx.x == 0) g_nbr_cnt[row] = min(cnt, MAXNBR);
}

// ---------------- sparse attention + residual: one block per (b,q) ----------
// 8 warps = 8 heads. Writes g_h = x + attn_out.
__global__ void attn_kernel(const float* __restrict__ x,
                            const float* __restrict__ stoich,
                            const float* __restrict__ gW,
                            const float* __restrict__ gb) {
    int row = blockIdx.x;
    int b = row >> 10;
    int tid = threadIdx.x;

    __shared__ float qrow[Dd];
    __shared__ float gate[MAXNBR];
    __shared__ int   nbr_s[MAXNBR];
    __shared__ float sc[Hh][MAXNBR];

    int cnt = g_nbr_cnt[row];

    // load q row (LN1 output) into smem: 256 float4
    ((float4*)qrow)[tid] = ((const float4*)(g_normed + (size_t)row * Dd))[tid];

    float st = stoich[row];
    for (int j = tid; j < cnt; j += 256) {
        int k = g_nbr_idx[row * MAXNBR + j];
        nbr_s[j] = k;
        gate[j] = 1.f / (1.f + expf(-(st * gW[k] + gb[k])));
    }
    __syncthreads();

    int wid = tid >> 5, lane = tid & 31;
    const float* base = g_normed + (size_t)b * Nn * Dd;
    float4 qv = ((const float4*)qrow)[wid * 32 + lane];

    const float scale = 0.08838834764831845f;  // 1/sqrt(128)
    float m = -INFINITY;
    for (int j = 0; j < cnt; j++) {
        int k = nbr_s[j];
        float4 kv = ((const float4*)(base + (size_t)k * Dd + wid * HD))[lane];
        float d = qv.x * kv.x + qv.y * kv.y + qv.z * kv.z + qv.w * kv.w;
#pragma unroll
        for (int o = 16; o; o >>= 1) d += __shfl_xor_sync(0xffffffffu, d, o);
        float s = d * scale * gate[j];
        if (lane == 0) sc[wid][j] = s;
        m = fmaxf(m, s);
    }
    __syncwarp();

    float Z = 0.f;
    for (int j = lane; j < cnt; j += 32) Z += expf(sc[wid][j] - m);
#pragma unroll
    for (int o = 16; o; o >>= 1) Z += __shfl_xor_sync(0xffffffffu, Z, o);
    float invZ = 1.f / Z;

    float4 acc = make_float4(0.f, 0.f, 0.f, 0.f);
    for (int j = 0; j < cnt; j++) {
        float p = expf(sc[wid][j] - m) * invZ;
        int k = nbr_s[j];
        float4 kv = ((const float4*)(base + (size_t)k * Dd + wid * HD))[lane];
        acc.x += p * kv.x; acc.y += p * kv.y; acc.z += p * kv.z; acc.w += p * kv.w;
    }

    size_t off = (size_t)row * Dd + wid * HD + lane * 4;
    float4 xv = *(const float4*)(x + off);
    float4 o4 = make_float4(xv.x + acc.x, xv.y + acc.y, xv.z + acc.z, xv.w + acc.w);
    *(float4*)(g_h + off) = o4;
}

// ---------------- SGEMM 128x128x16, 256 threads, 8x8 per thread -------------
__device__ __forceinline__ float gelu_exact(float v) {
    return 0.5f * v * (1.f + erff(v * 0.70710678118654752f));
}

template <int ACT>  // 1: gelu epilogue; 0: +residual epilogue
__global__ void sgemm_kernel(const float* __restrict__ A,
                             const float* __restrict__ B,
                             const float* __restrict__ bias,
                             const float* __restrict__ res,
                             float* __restrict__ C,
                             int M, int N, int K) {
    const int BK = 16, TM = 8, TN = 8;
    __shared__ float As[BK][128];
    __shared__ float Bs[BK][128];

    int tid = threadIdx.x;
    int br = blockIdx.y, bc = blockIdx.x;

    int aRow  = tid >> 2;   // 0..63
    int aCol4 = tid & 3;    // float4 slot in 16-wide K tile
    int bRow  = tid >> 5;   // 0..7
    int bCol4 = tid & 31;   // float4 slot in 128-wide N tile

    int tr = tid >> 4, tc = tid & 15;
    float acc[TM][TN] = {};

    for (int k0 = 0; k0 < K; k0 += BK) {
#pragma unroll
        for (int t = 0; t < 2; t++) {
            int r = aRow + t * 64;
            float4 v = *(const float4*)&A[(size_t)(br * 128 + r) * K + k0 + aCol4 * 4];
            As[aCol4 * 4 + 0][r] = v.x;
            As[aCol4 * 4 + 1][r] = v.y;
            As[aCol4 * 4 + 2][r] = v.z;
            As[aCol4 * 4 + 3][r] = v.w;
        }
#pragma unroll
        for (int t = 0; t < 2; t++) {
            int r = bRow + t * 8;
            float4 v = *(const float4*)&B[(size_t)(k0 + r) * N + bc * 128 + bCol4 * 4];
            *(float4*)&Bs[r][bCol4 * 4] = v;
        }
        __syncthreads();

#pragma unroll
        for (int kk = 0; kk < BK; kk++) {
            float ra[TM], rb[TN];
#pragma unroll
            for (int i = 0; i < TM; i++) ra[i] = As[kk][tr * TM + i];
#pragma unroll
            for (int j = 0; j < TN; j++) rb[j] = Bs[kk][tc * TN + j];
#pragma unroll
            for (int i = 0; i < TM; i++)
#pragma unroll
                for (int j = 0; j < TN; j++) acc[i][j] += ra[i] * rb[j];
        }
        __syncthreads();
    }

#pragma unroll
    for (int i = 0; i < TM; i++) {
        int row = br * 128 + tr * TM + i;
#pragma unroll
        for (int j = 0; j < TN; j++) {
            int col = bc * 128 + tc * TN + j;
            float v = acc[i][j] + bias[col];
            if (ACT) {
                v = gelu_exact(v);
            } else {
                v += res[(size_t)row * N + col];
            }
            C[(size_t)row * N + col] = v;
        }
    }
}

// ---------------- launch -----------------------------------------------------
extern "C" void kernel_launch(void* const* d_in, const int* in_sizes, int n_in,
                              void* d_out, int out_size) {
    const float* x      = (const float*)d_in[0];
    const int*   adj    = (const int*)d_in[1];
    const float* stoich = (const float*)d_in[2];
    const float* ln1_g  = (const float*)d_in[3];
    const float* ln1_b  = (const float*)d_in[4];
    const float* ln2_g  = (const float*)d_in[5];
    const float* ln2_b  = (const float*)d_in[6];
    const float* W1     = (const float*)d_in[7];
    const float* b1     = (const float*)d_in[8];
    const float* W2     = (const float*)d_in[9];
    const float* b2     = (const float*)d_in[10];
    const float* gW     = (const float*)d_in[11];
    const float* gb     = (const float*)d_in[12];
    float* out = (float*)d_out;

    float *normed, *hbuf, *normed2, *mlp1;
    cudaGetSymbolAddress((void**)&normed,  g_normed);
    cudaGetSymbolAddress((void**)&hbuf,    g_h);
    cudaGetSymbolAddress((void**)&normed2, g_normed2);
    cudaGetSymbolAddress((void**)&mlp1,    g_mlp1);

    // 1. LN1
    ln_kernel<<<ROWS, 256>>>(x, ln1_g, ln1_b, normed);
    // 2. neighbor lists
    build_nbr_kernel<<<ROWS, 256>>>(adj);
    // 3. sparse attention + residual -> g_h
    attn_kernel<<<ROWS, 256>>>(x, stoich, gW, gb);
    // 4. LN2
    ln_kernel<<<ROWS, 256>>>(hbuf, ln2_g, ln2_b, normed2);
    // 5. mlp1 = gelu(normed2 @ W1 + b1)   [4096 x 4096]
    {
        dim3 grid(4 * Dd / 128, ROWS / 128);
        sgemm_kernel<1><<<grid, 256>>>(normed2, W1, b1, nullptr, mlp1,
                                       ROWS, 4 * Dd, Dd);
    }
    // 6. out = mlp1 @ W2 + b2 + g_h      [4096 x 1024]
    {
        dim3 grid(Dd / 128, ROWS / 128);
        sgemm_kernel<0><<<grid, 256>>>(mlp1, W2, b2, hbuf, out,
                                       ROWS, Dd, 4 * Dd);
    }
}